// round 4
// baseline (speedup 1.0000x reference)
#include <cuda_runtime.h>

#define WW 512
#define NB 16
#define NPIX (WW * WW)
#define NITERS 10
#define INV_CELL 2.56f        // 1 / (200/512)

#define TX 128                // tile width  (cells)
#define TY 8                  // tile height (cells)
#define SH_W 136              // TX + 8 (halo 4 each side, keeps float4 alignment)
#define SH_H 12               // TY + 4 (halo 2 each side)

// Persistent scratch state (no allocations allowed in kernel_launch).
__device__ float g_tA[NB * NPIX];
__device__ float g_tB[NB * NPIX];
__device__ float g_sed[NB * NPIX];
__device__ float g_wat[NB * NPIX];
__device__ float g_vel[NB * NPIX];

template <bool FIRST, bool LAST>
__global__ void __launch_bounds__(256) erosion_step(
    const float* __restrict__ inp,
    const float* __restrict__ rain,
    const float* __restrict__ p_rr,
    const float* __restrict__ p_ev,
    const float* __restrict__ p_mhd,
    const float* __restrict__ p_heps,
    const float* __restrict__ p_grav,
    const float* __restrict__ p_scc,
    const float* __restrict__ p_diss,
    const float* __restrict__ p_depo,
    float* __restrict__ outp,
    int pp)
{
    __shared__ float sm[SH_H * SH_W];

    int b    = blockIdx.z;
    int base = b * NPIX;
    int row0 = blockIdx.y * TY;
    int col0 = blockIdx.x * TX;

    const float* tin = FIRST ? (inp + base) : ((pp ? g_tB : g_tA) + base);

    // ---- cooperative smem fill: 12 rows x 34 float4 groups, clamped ----
    for (int task = threadIdx.x; task < 34 * SH_H; task += 256) {
        int sr  = task / 34;
        int g   = task - sr * 34;
        int gr  = min(max(row0 - 2 + sr, 0), WW - 1);
        int gc0 = col0 - 4 + g * 4;
        const float* src = tin + gr * WW;
        float4 v;
        if ((unsigned)gc0 <= (unsigned)(WW - 4)) {
            v = __ldg((const float4*)(src + gc0));
        } else {
            v.x = __ldg(src + min(max(gc0,     0), WW - 1));
            v.y = __ldg(src + min(max(gc0 + 1, 0), WW - 1));
            v.z = __ldg(src + min(max(gc0 + 2, 0), WW - 1));
            v.w = __ldg(src + min(max(gc0 + 3, 0), WW - 1));
        }
        if (FIRST) {
            v.x = (1.0f - v.x) * 0.5f;
            v.y = (1.0f - v.y) * 0.5f;
            v.z = (1.0f - v.z) * 0.5f;
            v.w = (1.0f - v.w) * 0.5f;
        }
        *(float4*)(sm + sr * SH_W + g * 4) = v;
    }
    __syncthreads();

    int ty   = threadIdx.x >> 5;           // 0..7
    int tx4  = (threadIdx.x & 31) << 2;    // 0..124
    int r    = row0 + ty;
    int c4   = col0 + tx4;
    int rowo = r * WW + c4;

    const float* smc = sm + (ty + 2) * SH_W + tx4 + 4;

    float4 tc = *(const float4*)smc;
    float ta[4] = { tc.x, tc.y, tc.z, tc.w };

    // ---- dx (row stencil, from smem) ----
    float dxa[4];
    if (r == 0) {
        #pragma unroll
        for (int i = 0; i < 4; i++) dxa[i] = 0.5f * (ta[i] * 1.1f - ta[i]);
    } else if (r == WW - 1) {
        #pragma unroll
        for (int i = 0; i < 4; i++) dxa[i] = 0.5f * (ta[i] * 0.9f - ta[i]);
    } else {
        float4 tu = *(const float4*)(smc - SH_W);
        float4 td = *(const float4*)(smc + SH_W);
        dxa[0] = 0.5f * (td.x - tu.x);
        dxa[1] = 0.5f * (td.y - tu.y);
        dxa[2] = 0.5f * (td.z - tu.z);
        dxa[3] = 0.5f * (td.w - tu.w);
    }

    // ---- dy (column stencil, from smem) ----
    float tl  = smc[-1];
    float trr = smc[4];
    float dya[4];
    dya[0] = (c4 == 0)        ? 0.5f * (ta[0] * 1.1f - ta[0]) : 0.5f * (ta[1] - tl);
    dya[1] = 0.5f * (ta[2] - ta[0]);
    dya[2] = 0.5f * (ta[3] - ta[1]);
    dya[3] = (c4 == WW - 4)   ? 0.5f * (ta[3] * 0.9f - ta[3]) : 0.5f * (trr - ta[2]);

    // maskless gather valid for cells with r,c in [2, 509]
    bool interior = (r >= 2) && (r <= WW - 3) && (c4 >= 4) && (c4 <= WW - 8);

    // ---- scalar params ----
    float rr   = fmaxf(__ldg(p_rr), 0.0f);
    float ev   = fmaxf(__ldg(p_ev), 0.0f);
    float grav = fmaxf(__ldg(p_grav), 0.0f);
    float heps = 0.0f, mhd = 0.0f, scc = 0.0f, diss = 0.0f, depo = 0.0f;
    if (!FIRST) {
        heps = __ldg(p_heps);
        mhd  = __ldg(p_mhd);
        scc  = fmaxf(__ldg(p_scc), 0.0f);
        diss = __ldg(p_diss);
        depo = __ldg(p_depo);
    }

    float4 rn4 = __ldg((const float4*)(rain + rowo));
    float rna[4] = { rn4.x, rn4.y, rn4.z, rn4.w };

    float seda[4] = {0,0,0,0}, wata[4] = {0,0,0,0}, vela[4] = {0,0,0,0};
    if (!FIRST) {
        float4 s4 = __ldg((const float4*)(g_sed + base + rowo));
        float4 w4 = __ldg((const float4*)(g_wat + base + rowo));
        float4 v4 = __ldg((const float4*)(g_vel + base + rowo));
        seda[0]=s4.x; seda[1]=s4.y; seda[2]=s4.z; seda[3]=s4.w;
        wata[0]=w4.x; wata[1]=w4.y; wata[2]=w4.z; wata[3]=w4.w;
        vela[0]=v4.x; vela[1]=v4.y; vela[2]=v4.z; vela[3]=v4.w;
    }

    float oT[4], oS[4], oW[4], oV[4];

    #pragma unroll
    for (int i = 0; i < 4; i++) {
        int   c   = c4 + i;
        float t00 = ta[i];
        float dx  = dxa[i], dy = dya[i];

        // normalized gradient (factor == 0 always; noise path dead)
        float inv = rsqrtf(dx * dx + dy * dy + 1e-11f);
        float fdx = dx * inv;
        float fdy = dy * inv;

        // bilinear_sample(terrain, -gradient), taps served from smem
        float fx  = (float)c - fdx;
        float fy  = (float)r - fdy;
        float x0f = floorf(fx), y0f = floorf(fy);
        int   x0  = (int)x0f,  y0  = (int)y0f;
        float wx1 = fx - x0f,  wy1 = fy - y0f;

        float v00, v10, v01, v11;
        if (interior) {
            const float* p = sm + (y0 - row0 + 2) * SH_W + (x0 - col0 + 4);
            v00 = p[0]        - 1.0f;
            v10 = p[1]        - 1.0f;
            v01 = p[SH_W]     - 1.0f;
            v11 = p[SH_W + 1] - 1.0f;
        } else {
            int x1 = x0 + 1, y1 = y0 + 1;
            bool vx0 = (unsigned)x0 < (unsigned)WW;
            bool vx1 = (unsigned)x1 < (unsigned)WW;
            bool vy0 = (unsigned)y0 < (unsigned)WW;
            bool vy1 = (unsigned)y1 < (unsigned)WW;
            int lx0 = min(max(x0, 0), WW - 1) - col0 + 4;
            int lx1 = min(max(x1, 0), WW - 1) - col0 + 4;
            int ly0 = min(max(y0, 0), WW - 1) - row0 + 2;
            int ly1 = min(max(y1, 0), WW - 1) - row0 + 2;
            v00 = (vx0 & vy0) ? (sm[ly0 * SH_W + lx0] - 1.0f) : 0.0f;
            v10 = (vx1 & vy0) ? (sm[ly0 * SH_W + lx1] - 1.0f) : 0.0f;
            v01 = (vx0 & vy1) ? (sm[ly1 * SH_W + lx0] - 1.0f) : 0.0f;
            v11 = (vx1 & vy1) ? (sm[ly1 * SH_W + lx1] - 1.0f) : 0.0f;
        }
        float nbv = (1.0f - wy1) * ((1.0f - wx1) * v00 + wx1 * v10)
                  + wy1 * ((1.0f - wx1) * v01 + wx1 * v11) + 1.0f;
        float hd = t00 - nbv;

        if (FIRST) {
            // iter 0: sed == vel == 0 => dep == 0; terrain unchanged.
            float wat = rr * rna[i];
            float m1 = fmaxf(-fdy, 0.0f); if (c == WW - 1) m1 = 0.0f;
            float m2 = fmaxf(1.0f - fabsf(fdy), 0.0f);
            float m3 = fmaxf(fdy, 0.0f);  if (c == 0)      m3 = 0.0f;
            wat = (m1 * wat + m2 * wat) + m3 * wat;
            wat = wat * (1.0f - ev);
            oT[i] = t00;
            oS[i] = 0.0f;
            oW[i] = wat;
            oV[i] = grav * hd * INV_CELL;
        } else {
            float sed = seda[i];
            float wat = wata[i] + rr * rna[i];
            float vel = vela[i];

            float hds     = (hd - heps > 0.0f) ? 1.0f : 0.0f;
            float nhd     = hds * fmaxf(hd, mhd);
            float sed_cap = (nhd * INV_CELL) * vel * wat * scc;
            float ftb     = (hd < 0.0f) ? 1.0f : 0.0f;
            float first   = fminf(fmaxf(-hd, 0.0f), sed);
            float sdiff   = sed - sed_cap;
            float third   = (1.0f - ftb) *
                            (fmaxf(sdiff * depo, 0.0f) - fmaxf(-sdiff * diss, 0.0f));
            float dep     = fmaxf(-fmaxf(hd, 0.0f), first + third);

            float tnew = t00 + dep;
            if (LAST) {
                oT[i] = fmaxf(1.0f + (1.0f - tnew * 2.0f), 0.0f) - 1.0f;
            } else {
                sed = sed - dep;
                float m1 = fmaxf(-fdy, 0.0f); if (c == WW - 1) m1 = 0.0f;
                float m2 = fmaxf(1.0f - fabsf(fdy), 0.0f);
                float m3 = fmaxf(fdy, 0.0f);  if (c == 0)      m3 = 0.0f;
                sed = (m1 * sed + m2 * sed) + m3 * sed;
                wat = (m1 * wat + m2 * wat) + m3 * wat;
                wat = wat * (1.0f - ev);
                oT[i] = tnew;
                oS[i] = sed;
                oW[i] = wat;
                oV[i] = grav * hd * INV_CELL;
            }
        }
    }

    if (LAST) {
        *(float4*)(outp + base + rowo) = make_float4(oT[0], oT[1], oT[2], oT[3]);
    } else {
        float* tout = (pp ? g_tA : g_tB) + base;
        *(float4*)(tout + rowo)         = make_float4(oT[0], oT[1], oT[2], oT[3]);
        *(float4*)(g_sed + base + rowo) = make_float4(oS[0], oS[1], oS[2], oS[3]);
        *(float4*)(g_wat + base + rowo) = make_float4(oW[0], oW[1], oW[2], oW[3]);
        *(float4*)(g_vel + base + rowo) = make_float4(oV[0], oV[1], oV[2], oV[3]);
    }
}

extern "C" void kernel_launch(void* const* d_in, const int* in_sizes, int n_in,
                              void* d_out, int out_size) {
    const float* inp      = (const float*)d_in[0];
    const float* rainfall = (const float*)d_in[1];
    // d_in[2] = random_gradient: mathematically dead (factor == 0 always)
    const float* p_rr   = (const float*)d_in[3];
    const float* p_ev   = (const float*)d_in[4];
    const float* p_mhd  = (const float*)d_in[5];
    const float* p_heps = (const float*)d_in[6];
    const float* p_grav = (const float*)d_in[7];
    const float* p_scc  = (const float*)d_in[8];
    const float* p_diss = (const float*)d_in[9];
    const float* p_depo = (const float*)d_in[10];
    float* outp = (float*)d_out;

    dim3 grid(WW / TX, WW / TY, NB);   // (4, 64, 16)
    dim3 block(256);

    for (int it = 0; it < NITERS; ++it) {
        const float* rain = rainfall + it * NPIX;
        int pp = it & 1;
        if (it == 0) {
            erosion_step<true, false><<<grid, block>>>(
                inp, rain, p_rr, p_ev, p_mhd, p_heps, p_grav, p_scc, p_diss,
                p_depo, outp, pp);
        } else if (it == NITERS - 1) {
            erosion_step<false, true><<<grid, block>>>(
                inp, rain, p_rr, p_ev, p_mhd, p_heps, p_grav, p_scc, p_diss,
                p_depo, outp, pp);
        } else {
            erosion_step<false, false><<<grid, block>>>(
                inp, rain, p_rr, p_ev, p_mhd, p_heps, p_grav, p_scc, p_diss,
                p_depo, outp, pp);
        }
    }
}

// round 5
// speedup vs baseline: 1.0759x; 1.0759x over previous
#include <cuda_runtime.h>

#define WW 512
#define NB 16
#define NPIX (WW * WW)
#define NITERS 10
#define INV_CELL 2.56f        // 1 / (200/512)

// Persistent scratch state (no allocations allowed in kernel_launch).
__device__ float g_tA[NB * NPIX];
__device__ float g_tB[NB * NPIX];
__device__ float g_sed[NB * NPIX];
__device__ float g_wat[NB * NPIX];
__device__ float g_vel[NB * NPIX];

template <bool FIRST>
__device__ __forceinline__ float tval(float v) {
    return FIRST ? (1.0f - v) * 0.5f : v;
}

template <bool FIRST, bool LAST>
__global__ void __launch_bounds__(256, 5) erosion_step(
    const float* __restrict__ inp,
    const float* __restrict__ rain,
    const float* __restrict__ p_rr,
    const float* __restrict__ p_ev,
    const float* __restrict__ p_mhd,
    const float* __restrict__ p_heps,
    const float* __restrict__ p_grav,
    const float* __restrict__ p_scc,
    const float* __restrict__ p_diss,
    const float* __restrict__ p_depo,
    float* __restrict__ outp,
    int pp)
{
    int tid  = blockIdx.x * blockDim.x + threadIdx.x;   // 0 .. NPIX/4-1
    int b    = blockIdx.y;
    int base = b * NPIX;
    int c4   = (tid & 127) << 2;
    int r    = tid >> 7;
    int rowo = r * WW + c4;

    const float* tin = FIRST ? (inp + base) : ((pp ? g_tB : g_tA) + base);

    // ---- center row (float4) ----
    float4 tcv = __ldg((const float4*)(tin + rowo));
    float ta[4] = { tval<FIRST>(tcv.x), tval<FIRST>(tcv.y),
                    tval<FIRST>(tcv.z), tval<FIRST>(tcv.w) };

    // ---- dx (row stencil) ----
    float dxa[4];
    if (r == 0) {
        #pragma unroll
        for (int i = 0; i < 4; i++) dxa[i] = 0.5f * (ta[i] * 1.1f - ta[i]);
    } else if (r == WW - 1) {
        #pragma unroll
        for (int i = 0; i < 4; i++) dxa[i] = 0.5f * (ta[i] * 0.9f - ta[i]);
    } else {
        float4 tu = __ldg((const float4*)(tin + rowo - WW));
        float4 td = __ldg((const float4*)(tin + rowo + WW));
        dxa[0] = 0.5f * (tval<FIRST>(td.x) - tval<FIRST>(tu.x));
        dxa[1] = 0.5f * (tval<FIRST>(td.y) - tval<FIRST>(tu.y));
        dxa[2] = 0.5f * (tval<FIRST>(td.z) - tval<FIRST>(tu.z));
        dxa[3] = 0.5f * (tval<FIRST>(td.w) - tval<FIRST>(tu.w));
    }

    // ---- dy (column stencil within float4 + 2 halo scalars) ----
    float tl = (c4 > 0)   ? tval<FIRST>(__ldg(tin + rowo - 1)) : 0.0f;
    float tr = (c4 < 508) ? tval<FIRST>(__ldg(tin + rowo + 4)) : 0.0f;
    float dya[4];
    dya[0] = (c4 == 0)   ? 0.5f * (ta[0] * 1.1f - ta[0]) : 0.5f * (ta[1] - tl);
    dya[1] = 0.5f * (ta[2] - ta[0]);
    dya[2] = 0.5f * (ta[3] - ta[1]);
    dya[3] = (c4 == 508) ? 0.5f * (ta[3] * 0.9f - ta[3]) : 0.5f * (tr - ta[2]);

    bool interior = (r >= 1) && (r <= 509) && (c4 >= 4) && (c4 <= 504);

    // ---- scalar params ----
    float rr   = fmaxf(__ldg(p_rr), 0.0f);
    float ev   = fmaxf(__ldg(p_ev), 0.0f);
    float grav = fmaxf(__ldg(p_grav), 0.0f);
    float heps = 0.0f, mhd = 0.0f, scc = 0.0f, diss = 0.0f, depo = 0.0f;
    if (!FIRST) {
        heps = __ldg(p_heps);
        mhd  = __ldg(p_mhd);
        scc  = fmaxf(__ldg(p_scc), 0.0f);
        diss = __ldg(p_diss);
        depo = __ldg(p_depo);
    }

    float4 rn4 = __ldg((const float4*)(rain + rowo));

    float4 s4 = make_float4(0.f, 0.f, 0.f, 0.f);
    float4 w4 = make_float4(0.f, 0.f, 0.f, 0.f);
    float4 v4 = make_float4(0.f, 0.f, 0.f, 0.f);
    if (!FIRST) {
        s4 = __ldg((const float4*)(g_sed + base + rowo));
        w4 = __ldg((const float4*)(g_wat + base + rowo));
        v4 = __ldg((const float4*)(g_vel + base + rowo));
    }

    float4 oT, oS, oW, oV;
    float* pT = &oT.x; float* pS = &oS.x; float* pW = &oW.x; float* pV = &oV.x;
    const float* pRn = &rn4.x;
    const float* pSi = &s4.x; const float* pWi = &w4.x; const float* pVi = &v4.x;

    #pragma unroll
    for (int i = 0; i < 4; i++) {
        int   c   = c4 + i;
        float t00 = ta[i];
        float dx  = dxa[i], dy = dya[i];

        // normalized gradient (factor == 0 always; noise path dead)
        float inv = rsqrtf(dx * dx + dy * dy + 1e-11f);
        float fdx = dx * inv;
        float fdy = dy * inv;

        // bilinear_sample(terrain, -gradient)
        float fx  = (float)c - fdx;
        float fy  = (float)r - fdy;
        float x0f = floorf(fx), y0f = floorf(fy);
        int   x0  = (int)x0f,  y0  = (int)y0f;
        float wx1 = fx - x0f,  wy1 = fy - y0f;

        float v00, v10, v01, v11;
        if (interior) {
            const float* p = tin + y0 * WW + x0;
            v00 = tval<FIRST>(__ldg(p))          - 1.0f;
            v10 = tval<FIRST>(__ldg(p + 1))      - 1.0f;
            v01 = tval<FIRST>(__ldg(p + WW))     - 1.0f;
            v11 = tval<FIRST>(__ldg(p + WW + 1)) - 1.0f;
        } else {
            int x1 = x0 + 1, y1 = y0 + 1;
            bool vx0 = (unsigned)x0 < (unsigned)WW;
            bool vx1 = (unsigned)x1 < (unsigned)WW;
            bool vy0 = (unsigned)y0 < (unsigned)WW;
            bool vy1 = (unsigned)y1 < (unsigned)WW;
            int x0c = min(max(x0, 0), WW - 1), x1c = min(max(x1, 0), WW - 1);
            int y0c = min(max(y0, 0), WW - 1), y1c = min(max(y1, 0), WW - 1);
            const float* p0 = tin + y0c * WW;
            const float* p1 = tin + y1c * WW;
            v00 = (vx0 & vy0) ? (tval<FIRST>(__ldg(p0 + x0c)) - 1.0f) : 0.0f;
            v10 = (vx1 & vy0) ? (tval<FIRST>(__ldg(p0 + x1c)) - 1.0f) : 0.0f;
            v01 = (vx0 & vy1) ? (tval<FIRST>(__ldg(p1 + x0c)) - 1.0f) : 0.0f;
            v11 = (vx1 & vy1) ? (tval<FIRST>(__ldg(p1 + x1c)) - 1.0f) : 0.0f;
        }
        float nbv = (1.0f - wy1) * ((1.0f - wx1) * v00 + wx1 * v10)
                  + wy1 * ((1.0f - wx1) * v01 + wx1 * v11) + 1.0f;
        float hd = t00 - nbv;

        if (FIRST) {
            // iter 0: sed == vel == 0 => dep == 0; terrain unchanged.
            float wat = rr * pRn[i];
            float m1 = fmaxf(-fdy, 0.0f); if (c == WW - 1) m1 = 0.0f;
            float m2 = fmaxf(1.0f - fabsf(fdy), 0.0f);
            float m3 = fmaxf(fdy, 0.0f);  if (c == 0)      m3 = 0.0f;
            wat = (m1 * wat + m2 * wat) + m3 * wat;
            pT[i] = t00;
            pS[i] = 0.0f;
            pW[i] = wat * (1.0f - ev);
            pV[i] = grav * hd * INV_CELL;
        } else {
            float sed = pSi[i];
            float wat = pWi[i] + rr * pRn[i];
            float vel = pVi[i];

            float hds     = (hd - heps > 0.0f) ? 1.0f : 0.0f;
            float nhd     = hds * fmaxf(hd, mhd);
            float sed_cap = (nhd * INV_CELL) * vel * wat * scc;
            float ftb     = (hd < 0.0f) ? 1.0f : 0.0f;
            float first   = fminf(fmaxf(-hd, 0.0f), sed);
            float sdiff   = sed - sed_cap;
            float third   = (1.0f - ftb) *
                            (fmaxf(sdiff * depo, 0.0f) - fmaxf(-sdiff * diss, 0.0f));
            float dep     = fmaxf(-fmaxf(hd, 0.0f), first + third);

            float tnew = t00 + dep;
            if (LAST) {
                pT[i] = fmaxf(1.0f + (1.0f - tnew * 2.0f), 0.0f) - 1.0f;
            } else {
                sed = sed - dep;
                float m1 = fmaxf(-fdy, 0.0f); if (c == WW - 1) m1 = 0.0f;
                float m2 = fmaxf(1.0f - fabsf(fdy), 0.0f);
                float m3 = fmaxf(fdy, 0.0f);  if (c == 0)      m3 = 0.0f;
                sed = (m1 * sed + m2 * sed) + m3 * sed;
                wat = (m1 * wat + m2 * wat) + m3 * wat;
                pT[i] = tnew;
                pS[i] = sed;
                pW[i] = wat * (1.0f - ev);
                pV[i] = grav * hd * INV_CELL;
            }
        }
    }

    if (LAST) {
        *(float4*)(outp + base + rowo) = oT;
    } else {
        float* tout = (pp ? g_tA : g_tB) + base;
        *(float4*)(tout + rowo)         = oT;
        *(float4*)(g_sed + base + rowo) = oS;
        *(float4*)(g_wat + base + rowo) = oW;
        *(float4*)(g_vel + base + rowo) = oV;
    }
}

extern "C" void kernel_launch(void* const* d_in, const int* in_sizes, int n_in,
                              void* d_out, int out_size) {
    const float* inp      = (const float*)d_in[0];
    const float* rainfall = (const float*)d_in[1];
    // d_in[2] = random_gradient: mathematically dead (factor == 0 always)
    const float* p_rr   = (const float*)d_in[3];
    const float* p_ev   = (const float*)d_in[4];
    const float* p_mhd  = (const float*)d_in[5];
    const float* p_heps = (const float*)d_in[6];
    const float* p_grav = (const float*)d_in[7];
    const float* p_scc  = (const float*)d_in[8];
    const float* p_diss = (const float*)d_in[9];
    const float* p_depo = (const float*)d_in[10];
    float* outp = (float*)d_out;

    dim3 grid(NPIX / 4 / 256, NB);
    dim3 block(256);

    for (int it = 0; it < NITERS; ++it) {
        const float* rain = rainfall + it * NPIX;
        int pp = it & 1;
        if (it == 0) {
            erosion_step<true, false><<<grid, block>>>(
                inp, rain, p_rr, p_ev, p_mhd, p_heps, p_grav, p_scc, p_diss,
                p_depo, outp, pp);
        } else if (it == NITERS - 1) {
            erosion_step<false, true><<<grid, block>>>(
                inp, rain, p_rr, p_ev, p_mhd, p_heps, p_grav, p_scc, p_diss,
                p_depo, outp, pp);
        } else {
            erosion_step<false, false><<<grid, block>>>(
                inp, rain, p_rr, p_ev, p_mhd, p_heps, p_grav, p_scc, p_diss,
                p_depo, outp, pp);
        }
    }
}

// round 9
// speedup vs baseline: 1.0852x; 1.0087x over previous
#include <cuda_runtime.h>

#define WW 512
#define NB 16
#define NPIX (WW * WW)
#define NITERS 10
#define INV_CELL 2.56f        // 1 / (200/512)

// Persistent scratch state (no allocations allowed in kernel_launch).
__device__ float g_tA[NB * NPIX];
__device__ float g_tB[NB * NPIX];
__device__ float g_sed[NB * NPIX];
__device__ float g_wat[NB * NPIX];
__device__ float g_vel[NB * NPIX];

template <bool FIRST>
__device__ __forceinline__ float tval(float v) {
    return FIRST ? (1.0f - v) * 0.5f : v;
}

// Vertical micro-tile: thread = (column c, rows r0..r0+3); lanes are
// consecutive columns so every stencil/state access is coalesced and the
// scattered bilinear taps have per-warp spans of only ~3 rows x ~2 lines.
template <bool FIRST, bool LAST>
__global__ void __launch_bounds__(256) erosion_step(
    const float* __restrict__ inp,
    const float* __restrict__ rain,
    const float* __restrict__ p_rr,
    const float* __restrict__ p_ev,
    const float* __restrict__ p_mhd,
    const float* __restrict__ p_heps,
    const float* __restrict__ p_grav,
    const float* __restrict__ p_scc,
    const float* __restrict__ p_diss,
    const float* __restrict__ p_depo,
    float* __restrict__ outp,
    int pp)
{
    int c    = blockIdx.x * 256 + threadIdx.x;   // 0..511
    int r0   = blockIdx.y * 4;                   // 0..508
    int base = blockIdx.z * NPIX;

    const float* tin = FIRST ? (inp + base) : ((pp ? g_tB : g_tA) + base);

    // ---- terrain column r0-1 .. r0+4 (clamped; clamped rows only feed
    //      boundary formulas that ignore them) ----
    float tcol[6];
    #pragma unroll
    for (int j = 0; j < 6; j++) {
        int gr = min(max(r0 - 1 + j, 0), WW - 1);
        tcol[j] = tval<FIRST>(__ldg(tin + gr * WW + c));
    }

    // ---- horizontal neighbors via warp shuffle + halo loads on edge lanes ----
    float tl[4], trh[4];
    #pragma unroll
    for (int k = 0; k < 4; k++) {
        tl[k]  = __shfl_up_sync(0xffffffffu, tcol[k + 1], 1);
        trh[k] = __shfl_down_sync(0xffffffffu, tcol[k + 1], 1);
    }
    int lane = threadIdx.x & 31;
    if (lane == 0 && c > 0) {
        #pragma unroll
        for (int k = 0; k < 4; k++)
            tl[k] = tval<FIRST>(__ldg(tin + (r0 + k) * WW + (c - 1)));
    }
    if (lane == 31 && c < WW - 1) {
        #pragma unroll
        for (int k = 0; k < 4; k++)
            trh[k] = tval<FIRST>(__ldg(tin + (r0 + k) * WW + (c + 1)));
    }

    // ---- scalar params ----
    float rr   = fmaxf(__ldg(p_rr), 0.0f);
    float ev   = fmaxf(__ldg(p_ev), 0.0f);
    float grav = fmaxf(__ldg(p_grav), 0.0f);
    float heps = 0.0f, mhd = 0.0f, scc = 0.0f, diss = 0.0f, depo = 0.0f;
    if (!FIRST) {
        heps = __ldg(p_heps);
        mhd  = __ldg(p_mhd);
        scc  = fmaxf(__ldg(p_scc), 0.0f);
        diss = __ldg(p_diss);
        depo = __ldg(p_depo);
    }

    // ---- state + rain (coalesced scalar loads, batched for MLP) ----
    float rn[4], sed[4] = {0,0,0,0}, wat[4] = {0,0,0,0}, vel[4] = {0,0,0,0};
    #pragma unroll
    for (int k = 0; k < 4; k++) {
        int o = (r0 + k) * WW + c;
        rn[k] = __ldg(rain + o);
        if (!FIRST) {
            sed[k] = __ldg(g_sed + base + o);
            wat[k] = __ldg(g_wat + base + o);
            vel[k] = __ldg(g_vel + base + o);
        }
    }

    float* tout = LAST ? nullptr : ((pp ? g_tA : g_tB) + base);

    #pragma unroll
    for (int k = 0; k < 4; k++) {
        int   r   = r0 + k;
        int   o   = r * WW + c;
        float t00 = tcol[k + 1];

        float dx = (r == 0)      ? 0.5f * (t00 * 1.1f - t00)
                 : (r == WW - 1) ? 0.5f * (t00 * 0.9f - t00)
                 :                 0.5f * (tcol[k + 2] - tcol[k]);
        float dy = (c == 0)      ? 0.5f * (t00 * 1.1f - t00)
                 : (c == WW - 1) ? 0.5f * (t00 * 0.9f - t00)
                 :                 0.5f * (trh[k] - tl[k]);

        // normalized gradient (factor == 0 always; noise path dead)
        float inv = rsqrtf(dx * dx + dy * dy + 1e-11f);
        float fdx = dx * inv;
        float fdy = dy * inv;

        // bilinear_sample(terrain, -gradient)
        float fx  = (float)c - fdx;
        float fy  = (float)r - fdy;
        float x0f = floorf(fx), y0f = floorf(fy);
        int   x0  = (int)x0f,  y0  = (int)y0f;
        float wx1 = fx - x0f,  wy1 = fy - y0f;

        bool inter = (r >= 1) & (r <= WW - 3) & (c >= 1) & (c <= WW - 3);

        float v00, v10, v01, v11;
        if (inter) {
            const float* p = tin + y0 * WW + x0;
            v00 = tval<FIRST>(__ldg(p))          - 1.0f;
            v10 = tval<FIRST>(__ldg(p + 1))      - 1.0f;
            v01 = tval<FIRST>(__ldg(p + WW))     - 1.0f;
            v11 = tval<FIRST>(__ldg(p + WW + 1)) - 1.0f;
        } else {
            int x1 = x0 + 1, y1 = y0 + 1;
            bool vx0 = (unsigned)x0 < (unsigned)WW;
            bool vx1 = (unsigned)x1 < (unsigned)WW;
            bool vy0 = (unsigned)y0 < (unsigned)WW;
            bool vy1 = (unsigned)y1 < (unsigned)WW;
            int x0c = min(max(x0, 0), WW - 1), x1c = min(max(x1, 0), WW - 1);
            int y0c = min(max(y0, 0), WW - 1), y1c = min(max(y1, 0), WW - 1);
            const float* p0 = tin + y0c * WW;
            const float* p1 = tin + y1c * WW;
            v00 = (vx0 & vy0) ? (tval<FIRST>(__ldg(p0 + x0c)) - 1.0f) : 0.0f;
            v10 = (vx1 & vy0) ? (tval<FIRST>(__ldg(p0 + x1c)) - 1.0f) : 0.0f;
            v01 = (vx0 & vy1) ? (tval<FIRST>(__ldg(p1 + x0c)) - 1.0f) : 0.0f;
            v11 = (vx1 & vy1) ? (tval<FIRST>(__ldg(p1 + x1c)) - 1.0f) : 0.0f;
        }
        float nbv = (1.0f - wy1) * ((1.0f - wx1) * v00 + wx1 * v10)
                  + wy1 * ((1.0f - wx1) * v01 + wx1 * v11) + 1.0f;
        float hd = t00 - nbv;

        if (FIRST) {
            // iter 0: sed == vel == 0 => dep == 0; terrain unchanged.
            float w = rr * rn[k];
            float m1 = fmaxf(-fdy, 0.0f); if (c == WW - 1) m1 = 0.0f;
            float m2 = fmaxf(1.0f - fabsf(fdy), 0.0f);
            float m3 = fmaxf(fdy, 0.0f);  if (c == 0)      m3 = 0.0f;
            w = (m1 * w + m2 * w) + m3 * w;
            tout[o]          = t00;
            g_sed[base + o]  = 0.0f;
            g_wat[base + o]  = w * (1.0f - ev);
            g_vel[base + o]  = grav * hd * INV_CELL;
        } else {
            float s = sed[k];
            float w = wat[k] + rr * rn[k];
            float v = vel[k];

            float hds     = (hd - heps > 0.0f) ? 1.0f : 0.0f;
            float nhd     = hds * fmaxf(hd, mhd);
            float sed_cap = (nhd * INV_CELL) * v * w * scc;
            float ftb     = (hd < 0.0f) ? 1.0f : 0.0f;
            float first   = fminf(fmaxf(-hd, 0.0f), s);
            float sdiff   = s - sed_cap;
            float third   = (1.0f - ftb) *
                            (fmaxf(sdiff * depo, 0.0f) - fmaxf(-sdiff * diss, 0.0f));
            float dep     = fmaxf(-fmaxf(hd, 0.0f), first + third);

            float tnew = t00 + dep;
            if (LAST) {
                outp[base + o] = fmaxf(1.0f + (1.0f - tnew * 2.0f), 0.0f) - 1.0f;
            } else {
                s = s - dep;
                float m1 = fmaxf(-fdy, 0.0f); if (c == WW - 1) m1 = 0.0f;
                float m2 = fmaxf(1.0f - fabsf(fdy), 0.0f);
                float m3 = fmaxf(fdy, 0.0f);  if (c == 0)      m3 = 0.0f;
                s = (m1 * s + m2 * s) + m3 * s;
                w = (m1 * w + m2 * w) + m3 * w;
                tout[o]         = tnew;
                g_sed[base + o] = s;
                g_wat[base + o] = w * (1.0f - ev);
                g_vel[base + o] = grav * hd * INV_CELL;
            }
        }
    }
}

extern "C" void kernel_launch(void* const* d_in, const int* in_sizes, int n_in,
                              void* d_out, int out_size) {
    const float* inp      = (const float*)d_in[0];
    const float* rainfall = (const float*)d_in[1];
    // d_in[2] = random_gradient: mathematically dead (factor == 0 always)
    const float* p_rr   = (const float*)d_in[3];
    const float* p_ev   = (const float*)d_in[4];
    const float* p_mhd  = (const float*)d_in[5];
    const float* p_heps = (const float*)d_in[6];
    const float* p_grav = (const float*)d_in[7];
    const float* p_scc  = (const float*)d_in[8];
    const float* p_diss = (const float*)d_in[9];
    const float* p_depo = (const float*)d_in[10];
    float* outp = (float*)d_out;

    dim3 grid(WW / 256, WW / 4, NB);   // (2, 128, 16)
    dim3 block(256);

    for (int it = 0; it < NITERS; ++it) {
        const float* rain = rainfall + it * NPIX;
        int pp = it & 1;
        if (it == 0) {
            erosion_step<true, false><<<grid, block>>>(
                inp, rain, p_rr, p_ev, p_mhd, p_heps, p_grav, p_scc, p_diss,
                p_depo, outp, pp);
        } else if (it == NITERS - 1) {
            erosion_step<false, true><<<grid, block>>>(
                inp, rain, p_rr, p_ev, p_mhd, p_heps, p_grav, p_scc, p_diss,
                p_depo, outp, pp);
        } else {
            erosion_step<false, false><<<grid, block>>>(
                inp, rain, p_rr, p_ev, p_mhd, p_heps, p_grav, p_scc, p_diss,
                p_depo, outp, pp);
        }
    }
}